// round 11
// baseline (speedup 1.0000x reference)
#include <cuda_runtime.h>
#include <cuda_fp16.h>
#include <math.h>
#include <stdint.h>

// Problem dims (fixed)
#define B_    4
#define N_    1024
#define D_    256
#define H_    8
#define HD_   32
#define FFN_  1024
#define ROWS  (B_*N_)          // 4096
#define LN_EPS 1e-5f

// ---------------- scratch (static device memory; no allocs) ----------------
__device__ __align__(16) __half g_qksum_h[ROWS*D_];    // fp16(embed+query_pos)
__device__ __align__(16) __half g_embed_h[ROWS*D_];    // fp16(embed)
__device__ __align__(16) __half g_ipw_h[3*D_*D_];      // fp16 in_proj_w (768x256)
__device__ __align__(16) __half g_outw_h[D_*D_];
__device__ __align__(16) __half g_w1_h[FFN_*D_];
__device__ __align__(16) __half g_w2_h[D_*FFN_];
__device__ __align__(16) __half g_tauw_h[H_*D_];
__device__ __align__(16) __half g_qk_h[ROWS*2*D_];     // [q(256)|k(256)] fp16
__device__ __align__(16) __half g_v_h [ROWS*D_];
__device__ __align__(16) __half g_ctx_h[ROWS*D_];
__device__ __align__(16) __half g_x_h[ROWS*D_];
__device__ __align__(16) __half g_hh [ROWS*FFN_];
__device__ float g_x[ROWS*D_];

// ---------------- helpers ---------------------------------------------------
__device__ __forceinline__ void mma16(float* c, const uint32_t* a, uint32_t b0, uint32_t b1) {
    asm volatile(
        "mma.sync.aligned.m16n8k16.row.col.f32.f16.f16.f32 "
        "{%0,%1,%2,%3}, {%4,%5,%6,%7}, {%8,%9}, {%0,%1,%2,%3};\n"
        : "+f"(c[0]), "+f"(c[1]), "+f"(c[2]), "+f"(c[3])
        : "r"(a[0]), "r"(a[1]), "r"(a[2]), "r"(a[3]), "r"(b0), "r"(b1));
}
__device__ __forceinline__ void ldsm4(uint32_t* r, uint32_t addr) {
    asm volatile("ldmatrix.sync.aligned.m8n8.x4.shared.b16 {%0,%1,%2,%3}, [%4];"
        : "=r"(r[0]), "=r"(r[1]), "=r"(r[2]), "=r"(r[3]) : "r"(addr));
}
__device__ __forceinline__ void ldsm4t(uint32_t* r, uint32_t addr) {
    asm volatile("ldmatrix.sync.aligned.m8n8.x4.trans.shared.b16 {%0,%1,%2,%3}, [%4];"
        : "=r"(r[0]), "=r"(r[1]), "=r"(r[2]), "=r"(r[3]) : "r"(addr));
}
__device__ __forceinline__ uint32_t packh2(float lo, float hi) {
    __half2 p = __floats2half2_rn(lo, hi);
    return *reinterpret_cast<uint32_t*>(&p);
}
__device__ __forceinline__ uint32_t smaddr(const void* p) {
    return (uint32_t)__cvta_generic_to_shared(p);
}
__device__ __forceinline__ void cp16(uint32_t dst, const void* src) {
    asm volatile("cp.async.cg.shared.global [%0], [%1], 16;\n" :: "r"(dst), "l"(src));
}
__device__ __forceinline__ void cpcommit() { asm volatile("cp.async.commit_group;\n" ::: "memory"); }
__device__ __forceinline__ void cpwait1()  { asm volatile("cp.async.wait_group 1;\n" ::: "memory"); }
__device__ __forceinline__ void cpwait0()  { asm volatile("cp.async.wait_group 0;\n" ::: "memory"); }

#define HST 40

// ---------------- prep + weight convert (single launch) ---------------------
#define NP (ROWS*D_/4)       // 262144 float4 elements for prep
#define S0 49152             // in_proj_w 768*256/4
#define S1 (S0+16384)        // out_w
#define S2 (S1+65536)        // w1
#define S3 (S2+65536)        // w2
#define S4 (S3+512)          // tau_w
__global__ void prepconv_kernel(
    const float* __restrict__ e, const float* __restrict__ qp,
    __half* __restrict__ qksh, __half* __restrict__ eh,
    const float* __restrict__ ipw, const float* __restrict__ ow,
    const float* __restrict__ w1, const float* __restrict__ w2,
    const float* __restrict__ tw,
    __half* __restrict__ ipwh, __half* __restrict__ owh,
    __half* __restrict__ w1h, __half* __restrict__ w2h,
    __half* __restrict__ twh)
{
    int i = blockIdx.x * blockDim.x + threadIdx.x;
    if (i < NP) {
        float4 ev = ((const float4*)e)[i];
        float4 qv = ((const float4*)qp)[i];
        __half2 s01 = __floats2half2_rn(ev.x + qv.x, ev.y + qv.y);
        __half2 s23 = __floats2half2_rn(ev.z + qv.z, ev.w + qv.w);
        __half2 e01 = __floats2half2_rn(ev.x, ev.y);
        __half2 e23 = __floats2half2_rn(ev.z, ev.w);
        uint2 su = {*(uint32_t*)&s01, *(uint32_t*)&s23};
        uint2 eu = {*(uint32_t*)&e01, *(uint32_t*)&e23};
        ((uint2*)qksh)[i] = su;
        ((uint2*)eh)[i]   = eu;
        return;
    }
    int j = i - NP;
    const float* src; __half* dst; int k;
    if      (j < S0) { src = ipw; dst = ipwh; k = j; }
    else if (j < S1) { src = ow;  dst = owh;  k = j - S0; }
    else if (j < S2) { src = w1;  dst = w1h;  k = j - S1; }
    else if (j < S3) { src = w2;  dst = w2h;  k = j - S2; }
    else if (j < S4) { src = tw;  dst = twh;  k = j - S3; }
    else return;
    float4 v = ((const float4*)src)[k];
    __half2 a = __floats2half2_rn(v.x, v.y);
    __half2 b = __floats2half2_rn(v.z, v.w);
    uint2 u = {*(uint32_t*)&a, *(uint32_t*)&b};
    ((uint2*)dst)[k] = u;
}

// ---------------- 64x64 fp16 GEMM body (3-stage cp.async) -------------------
__device__ __forceinline__ void gemm64_body(
    const __half* __restrict__ A, const __half* __restrict__ Wrow,
    const float* __restrict__ biasc, const float* __restrict__ resid,
    void* __restrict__ Cv, int ldC, int bm, int cn,
    int K, int relu, int half_out, __half* As, __half* Ws)
{
    const int tid = threadIdx.x;
    const int warp = tid >> 5, lane = tid & 31;
    const int grp = lane >> 2, t4 = lane & 3;
    const int wm = warp >> 1, wn = warp & 1;
    const int KT = K >> 5;
    const int r8a = ((lane >> 3) & 1) * 8 + (lane & 7);
    const int c8a = ((lane >> 4) & 1) * 8;
    const int r8b = ((lane >> 4) & 1) * 8 + (lane & 7);
    const int c8b = ((lane >> 3) & 1) * 8;
    const int lr = tid >> 2, lseg = tid & 3;
    const int lr2 = lr + 32;

    #pragma unroll
    for (int p = 0; p < 2; p++) {
        if (p < KT) {
            const int k0 = p * 32;
            cp16(smaddr(&As[p * 64 * HST + lr * HST + lseg * 8]),  &A[(size_t)(bm + lr) * K + k0 + lseg * 8]);
            cp16(smaddr(&As[p * 64 * HST + lr2 * HST + lseg * 8]), &A[(size_t)(bm + lr2) * K + k0 + lseg * 8]);
            cp16(smaddr(&Ws[p * 64 * HST + lr * HST + lseg * 8]),  &Wrow[(size_t)lr * K + k0 + lseg * 8]);
            cp16(smaddr(&Ws[p * 64 * HST + lr2 * HST + lseg * 8]), &Wrow[(size_t)lr2 * K + k0 + lseg * 8]);
            cpcommit();
        }
    }

    float acc[2][4][4] = {};
    for (int kt = 0; kt < KT; kt++) {
        const int st = kt % 3;
        if (kt + 1 < KT) cpwait1(); else cpwait0();
        __syncthreads();
        if (kt + 2 < KT) {
            const int ns = (kt + 2) % 3;
            const int k0 = (kt + 2) * 32;
            cp16(smaddr(&As[ns * 64 * HST + lr * HST + lseg * 8]),  &A[(size_t)(bm + lr) * K + k0 + lseg * 8]);
            cp16(smaddr(&As[ns * 64 * HST + lr2 * HST + lseg * 8]), &A[(size_t)(bm + lr2) * K + k0 + lseg * 8]);
            cp16(smaddr(&Ws[ns * 64 * HST + lr * HST + lseg * 8]),  &Wrow[(size_t)lr * K + k0 + lseg * 8]);
            cp16(smaddr(&Ws[ns * 64 * HST + lr2 * HST + lseg * 8]), &Wrow[(size_t)lr2 * K + k0 + lseg * 8]);
            cpcommit();
        }
        __half* Ab = &As[st * 64 * HST];
        __half* Wb = &Ws[st * 64 * HST];
        uint32_t af[2][2][4], bf[2][2][4];
        #pragma unroll
        for (int mf = 0; mf < 2; mf++)
            #pragma unroll
            for (int s = 0; s < 2; s++)
                ldsm4(af[mf][s], smaddr(&Ab[(wm * 32 + mf * 16 + r8a) * HST + s * 16 + c8a]));
        #pragma unroll
        for (int nb2 = 0; nb2 < 2; nb2++)
            #pragma unroll
            for (int s = 0; s < 2; s++)
                ldsm4(bf[nb2][s], smaddr(&Wb[(wn * 32 + nb2 * 16 + r8b) * HST + s * 16 + c8b]));
        #pragma unroll
        for (int mf = 0; mf < 2; mf++)
            #pragma unroll
            for (int nb2 = 0; nb2 < 2; nb2++)
                #pragma unroll
                for (int s = 0; s < 2; s++) {
                    mma16(acc[mf][2 * nb2],     af[mf][s], bf[nb2][s][0], bf[nb2][s][1]);
                    mma16(acc[mf][2 * nb2 + 1], af[mf][s], bf[nb2][s][2], bf[nb2][s][3]);
                }
        __syncthreads();
    }

    #pragma unroll
    for (int mf = 0; mf < 2; mf++) {
        int r0 = bm + wm * 32 + mf * 16 + grp;
        #pragma unroll
        for (int nf = 0; nf < 4; nf++) {
            int cl = wn * 32 + (nf >> 1) * 16 + (nf & 1) * 8 + 2 * t4;
            int c0 = cn + cl;
            float b0v = biasc[cl], b1v = biasc[cl + 1];
            float v0 = acc[mf][nf][0] + b0v, v1 = acc[mf][nf][1] + b1v;
            float v2 = acc[mf][nf][2] + b0v, v3 = acc[mf][nf][3] + b1v;
            if (resid) {
                v0 += resid[(size_t)r0 * ldC + c0];
                v1 += resid[(size_t)r0 * ldC + c0 + 1];
                v2 += resid[(size_t)(r0 + 8) * ldC + c0];
                v3 += resid[(size_t)(r0 + 8) * ldC + c0 + 1];
            }
            if (relu) {
                v0 = fmaxf(v0, 0.f); v1 = fmaxf(v1, 0.f);
                v2 = fmaxf(v2, 0.f); v3 = fmaxf(v3, 0.f);
            }
            if (half_out) {
                __half* Ch = (__half*)Cv;
                *(__half2*)&Ch[(size_t)r0 * ldC + c0]       = __floats2half2_rn(v0, v1);
                *(__half2*)&Ch[(size_t)(r0 + 8) * ldC + c0] = __floats2half2_rn(v2, v3);
            } else {
                float* C = (float*)Cv;
                float2 p0 = {v0, v1}, p1 = {v2, v3};
                *(float2*)&C[(size_t)r0 * ldC + c0] = p0;
                *(float2*)&C[(size_t)(r0 + 8) * ldC + c0] = p1;
            }
        }
    }
}

__global__ __launch_bounds__(128) void hgemm64_kernel(
    const __half* __restrict__ A, const __half* __restrict__ W,
    const float* __restrict__ bias, const float* __restrict__ resid,
    void* __restrict__ Cv, int Nc, int K, int relu, int half_out)
{
    __shared__ __half As[3][64 * HST];
    __shared__ __half Ws[3][64 * HST];
    const int bm = blockIdx.y * 64, bn = blockIdx.x * 64;
    gemm64_body(A, W + (size_t)bn * K, bias + bn, resid, Cv, Nc, bm, bn,
                K, relu, half_out, &As[0][0], &Ws[0][0]);
}

// fused QKV: bx<8 -> [q|k] from qksum; bx>=8 -> v from embed
__global__ __launch_bounds__(128) void qkv_kernel(
    const __half* __restrict__ qksh, const __half* __restrict__ eh,
    const __half* __restrict__ ipwh, const float* __restrict__ ipb,
    __half* __restrict__ qkh, __half* __restrict__ vh)
{
    __shared__ __half As[3][64 * HST];
    __shared__ __half Ws[3][64 * HST];
    const int bx = blockIdx.x, bm = blockIdx.y * 64;
    if (bx < 8) {
        const int bn = bx * 64;
        gemm64_body(qksh, ipwh + (size_t)bn * D_, ipb + bn, nullptr, qkh, 512, bm, bn,
                    D_, 0, 1, &As[0][0], &Ws[0][0]);
    } else {
        const int bn = (bx - 8) * 64;
        gemm64_body(eh, ipwh + (size_t)(512 + bn) * D_, ipb + 512 + bn, nullptr, vh, 256, bm, bn,
                    D_, 0, 1, &As[0][0], &Ws[0][0]);
    }
}

// ---------------- fused GEMM(+bias+residual) + LayerNorm --------------------
// BM=32, BN=256 (full row per CTA). A[M,K] fp16, W[256,K] fp16, resid fp32.
// out = LN(A@W^T + bias + resid); writes fp32 (outf) and optional fp16 (outh).
__global__ __launch_bounds__(256) void gemm_ln_kernel(
    const __half* __restrict__ A, const __half* __restrict__ W,
    const float* __restrict__ bias, const float* __restrict__ resid,
    const float* __restrict__ g, const float* __restrict__ beta,
    float* __restrict__ outf, __half* __restrict__ outh, int K)
{
    extern __shared__ __half dyn[];
    __half* As = dyn;                     // [3][32*HST]
    __half* Ws = dyn + 3 * 32 * HST;      // [3][256*HST]
    __shared__ float red[2][32][8];

    const int tid = threadIdx.x;
    const int warp = tid >> 5, lane = tid & 31;
    const int grp = lane >> 2, t4 = lane & 3;
    const int bm = blockIdx.x * 32;
    const int KT = K >> 5;
    const int r8a = ((lane >> 3) & 1) * 8 + (lane & 7);
    const int c8a = ((lane >> 4) & 1) * 8;
    const int r8b = ((lane >> 4) & 1) * 8 + (lane & 7);
    const int c8b = ((lane >> 3) & 1) * 8;
    const int lr = tid >> 2, lseg = tid & 3;   // A rows (tid<128), W rows (+64*rep)

    // prefetch k-tiles 0,1
    #pragma unroll
    for (int p = 0; p < 2; p++) {
        if (p < KT) {
            const int k0 = p * 32;
            if (tid < 128)
                cp16(smaddr(&As[p * 32 * HST + lr * HST + lseg * 8]),
                     &A[(size_t)(bm + lr) * K + k0 + lseg * 8]);
            #pragma unroll
            for (int rep = 0; rep < 4; rep++) {
                int row = lr + rep * 64;
                cp16(smaddr(&Ws[p * 256 * HST + row * HST + lseg * 8]),
                     &W[(size_t)row * K + k0 + lseg * 8]);
            }
            cpcommit();
        }
    }

    float acc[2][4][4] = {};
    for (int kt = 0; kt < KT; kt++) {
        const int st = kt % 3;
        if (kt + 1 < KT) cpwait1(); else cpwait0();
        __syncthreads();
        if (kt + 2 < KT) {
            const int ns = (kt + 2) % 3;
            const int k0 = (kt + 2) * 32;
            if (tid < 128)
                cp16(smaddr(&As[ns * 32 * HST + lr * HST + lseg * 8]),
                     &A[(size_t)(bm + lr) * K + k0 + lseg * 8]);
            #pragma unroll
            for (int rep = 0; rep < 4; rep++) {
                int row = lr + rep * 64;
                cp16(smaddr(&Ws[ns * 256 * HST + row * HST + lseg * 8]),
                     &W[(size_t)row * K + k0 + lseg * 8]);
            }
            cpcommit();
        }
        __half* Ab = &As[st * 32 * HST];
        __half* Wb = &Ws[st * 256 * HST];
        uint32_t af[2][2][4], bf[2][2][4];
        #pragma unroll
        for (int mf = 0; mf < 2; mf++)
            #pragma unroll
            for (int s = 0; s < 2; s++)
                ldsm4(af[mf][s], smaddr(&Ab[(mf * 16 + r8a) * HST + s * 16 + c8a]));
        #pragma unroll
        for (int nb2 = 0; nb2 < 2; nb2++)
            #pragma unroll
            for (int s = 0; s < 2; s++)
                ldsm4(bf[nb2][s], smaddr(&Wb[(warp * 32 + nb2 * 16 + r8b) * HST + s * 16 + c8b]));
        #pragma unroll
        for (int mf = 0; mf < 2; mf++)
            #pragma unroll
            for (int nb2 = 0; nb2 < 2; nb2++)
                #pragma unroll
                for (int s = 0; s < 2; s++) {
                    mma16(acc[mf][2 * nb2],     af[mf][s], bf[nb2][s][0], bf[nb2][s][1]);
                    mma16(acc[mf][2 * nb2 + 1], af[mf][s], bf[nb2][s][2], bf[nb2][s][3]);
                }
        __syncthreads();
    }

    // bias + residual (in place), per-row partial sums
    #pragma unroll
    for (int mf = 0; mf < 2; mf++) {
        int rA = bm + mf * 16 + grp;
        float sA = 0.f, qA = 0.f, sB = 0.f, qB = 0.f;
        #pragma unroll
        for (int nf = 0; nf < 4; nf++) {
            int c0 = warp * 32 + (nf >> 1) * 16 + (nf & 1) * 8 + 2 * t4;
            float b0v = bias[c0], b1v = bias[c0 + 1];
            float v0 = acc[mf][nf][0] + b0v + resid[(size_t)rA * D_ + c0];
            float v1 = acc[mf][nf][1] + b1v + resid[(size_t)rA * D_ + c0 + 1];
            float v2 = acc[mf][nf][2] + b0v + resid[(size_t)(rA + 8) * D_ + c0];
            float v3 = acc[mf][nf][3] + b1v + resid[(size_t)(rA + 8) * D_ + c0 + 1];
            acc[mf][nf][0] = v0; acc[mf][nf][1] = v1;
            acc[mf][nf][2] = v2; acc[mf][nf][3] = v3;
            sA += v0 + v1; qA += v0 * v0 + v1 * v1;
            sB += v2 + v3; qB += v2 * v2 + v3 * v3;
        }
        sA += __shfl_xor_sync(0xffffffffu, sA, 1); sA += __shfl_xor_sync(0xffffffffu, sA, 2);
        qA += __shfl_xor_sync(0xffffffffu, qA, 1); qA += __shfl_xor_sync(0xffffffffu, qA, 2);
        sB += __shfl_xor_sync(0xffffffffu, sB, 1); sB += __shfl_xor_sync(0xffffffffu, sB, 2);
        qB += __shfl_xor_sync(0xffffffffu, qB, 1); qB += __shfl_xor_sync(0xffffffffu, qB, 2);
        if (t4 == 0) {
            red[0][mf * 16 + grp][warp] = sA;  red[1][mf * 16 + grp][warp] = qA;
            red[0][mf * 16 + 8 + grp][warp] = sB; red[1][mf * 16 + 8 + grp][warp] = qB;
        }
    }
    __syncthreads();

    #pragma unroll
    for (int mf = 0; mf < 2; mf++) {
        int rA = bm + mf * 16 + grp;
        float tA = 0.f, uA = 0.f, tB = 0.f, uB = 0.f;
        #pragma unroll
        for (int w = 0; w < 8; w++) {
            tA += red[0][mf * 16 + grp][w];     uA += red[1][mf * 16 + grp][w];
            tB += red[0][mf * 16 + 8 + grp][w]; uB += red[1][mf * 16 + 8 + grp][w];
        }
        float mA = tA * (1.0f / D_), vA = uA * (1.0f / D_) - mA * mA;
        float mB = tB * (1.0f / D_), vB = uB * (1.0f / D_) - mB * mB;
        float rsA = rsqrtf(vA + LN_EPS), rsB = rsqrtf(vB + LN_EPS);
        #pragma unroll
        for (int nf = 0; nf < 4; nf++) {
            int c0 = warp * 32 + (nf >> 1) * 16 + (nf & 1) * 8 + 2 * t4;
            float g0 = g[c0], g1v = g[c0 + 1], be0 = beta[c0], be1 = beta[c0 + 1];
            float o0 = (acc[mf][nf][0] - mA) * rsA * g0  + be0;
            float o1 = (acc[mf][nf][1] - mA) * rsA * g1v + be1;
            float o2 = (acc[mf][nf][2] - mB) * rsB * g0  + be0;
            float o3 = (acc[mf][nf][3] - mB) * rsB * g1v + be1;
            float2 p0 = {o0, o1}, p1 = {o2, o3};
            *(float2*)&outf[(size_t)rA * D_ + c0] = p0;
            *(float2*)&outf[(size_t)(rA + 8) * D_ + c0] = p1;
            if (outh) {
                *(__half2*)&outh[(size_t)rA * D_ + c0]       = __floats2half2_rn(o0, o1);
                *(__half2*)&outh[(size_t)(rA + 8) * D_ + c0] = __floats2half2_rn(o2, o3);
            }
        }
    }
}

// ---------------- fp16 flash attention (tau fused in prologue) --------------
#define BQ 128
#define JT 64
#define HSTR 40
#define NTILES (N_/JT)
__global__ __launch_bounds__(256, 2) void flash_attn_kernel(
    const __half* __restrict__ qh, const __half* __restrict__ vh,
    const __half* __restrict__ eh, const __half* __restrict__ twh,
    const float* __restrict__ tbias, const float* __restrict__ dist,
    __half* __restrict__ ctxh)
{
    __shared__ __half Qs[BQ * HSTR];
    __shared__ __half Ks[2][JT * HSTR];
    __shared__ __half Vs[2][JT * HSTR];
    __shared__ __half tws[D_];
    __shared__ float taus[BQ];

    const int bh = blockIdx.y;
    const int b = bh >> 3, h = bh & 7;
    const int i0 = blockIdx.x * BQ;
    const int tid = threadIdx.x;
    const int warp = tid >> 5, lane = tid & 31;
    const int grp = lane >> 2, t4 = lane & 3;
    const int wb = warp * 16;
    const int row_a = wb + grp, row_b = row_a + 8;

    const int r8a = ((lane >> 3) & 1) * 8 + (lane & 7);
    const int c8a = ((lane >> 4) & 1) * 8;
    const int r8b = ((lane >> 4) & 1) * 8 + (lane & 7);
    const int c8b = ((lane >> 3) & 1) * 8;

    {
        #pragma unroll
        for (int rep = 0; rep < 2; rep++) {
            int idx = tid + rep * 256;
            int r = idx >> 2, seg = idx & 3;
            cp16(smaddr(&Qs[r * HSTR + seg * 8]),
                 &qh[(size_t)(b * N_ + i0 + r) * (2 * D_) + h * HD_ + seg * 8]);
        }
        int r = tid >> 2, seg = tid & 3;
        cp16(smaddr(&Ks[0][r * HSTR + seg * 8]),
             &qh[(size_t)(b * N_ + r) * (2 * D_) + D_ + h * HD_ + seg * 8]);
        cp16(smaddr(&Vs[0][r * HSTR + seg * 8]),
             &vh[(size_t)(b * N_ + r) * D_ + h * HD_ + seg * 8]);
        cpcommit();
    }

    tws[tid] = twh[h * D_ + tid];
    __syncthreads();
    {
        const int trow = tid >> 1, thalf = tid & 1;
        const __half2* e2 = (const __half2*)&eh[(size_t)(b * N_ + i0 + trow) * D_ + thalf * 128];
        const __half2* w2 = (const __half2*)&tws[thalf * 128];
        float s = 0.f;
        #pragma unroll
        for (int k = 0; k < 64; k++) {
            float2 ef = __half22float2(e2[k]);
            float2 wf = __half22float2(w2[k]);
            s += ef.x * wf.x + ef.y * wf.y;
        }
        s += __shfl_xor_sync(0xffffffffu, s, 1);
        if (thalf == 0) taus[trow] = s + tbias[h];
    }
    __syncthreads();

    const float tau_a = taus[row_a];
    const float tau_b2 = taus[row_b];
    const float scale = 0.17677669529663688f;
    float m_a = -1e30f, m_b = -1e30f, l_a = 0.f, l_b = 0.f;
    float O[4][4] = {};
    uint32_t qa[2][4];

    for (int t = 0; t < NTILES; t++) {
        const int buf = t & 1;
        if (t + 1 < NTILES) {
            const int nb = buf ^ 1;
            int r = tid >> 2, seg = tid & 3;
            int j1 = (t + 1) * JT;
            cp16(smaddr(&Ks[nb][r * HSTR + seg * 8]),
                 &qh[(size_t)(b * N_ + j1 + r) * (2 * D_) + D_ + h * HD_ + seg * 8]);
            cp16(smaddr(&Vs[nb][r * HSTR + seg * 8]),
                 &vh[(size_t)(b * N_ + j1 + r) * D_ + h * HD_ + seg * 8]);
            cpcommit();
            cpwait1();
        } else {
            cpwait0();
        }
        __syncthreads();

        if (t == 0) {
            #pragma unroll
            for (int s = 0; s < 2; s++)
                ldsm4(qa[s], smaddr(&Qs[(wb + r8a) * HSTR + s * 16 + c8a]));
        }

        float acc[8][4] = {};
        #pragma unroll
        for (int s = 0; s < 2; s++) {
            #pragma unroll
            for (int nf2 = 0; nf2 < 4; nf2++) {
                uint32_t kb4[4];
                ldsm4(kb4, smaddr(&Ks[buf][(nf2 * 16 + r8b) * HSTR + s * 16 + c8b]));
                mma16(acc[2 * nf2],     qa[s], kb4[0], kb4[1]);
                mma16(acc[2 * nf2 + 1], qa[s], kb4[2], kb4[3]);
            }
        }

        const int j0 = t * JT;
        float mn_a = -1e30f, mn_b = -1e30f;
        #pragma unroll
        for (int nf = 0; nf < 8; nf++) {
            float2 da = *(const float2*)&dist[(size_t)(b * N_ + i0 + row_a) * N_ + j0 + nf * 8 + 2 * t4];
            float2 db = *(const float2*)&dist[(size_t)(b * N_ + i0 + row_b) * N_ + j0 + nf * 8 + 2 * t4];
            acc[nf][0] = acc[nf][0] * scale + da.x * tau_a;
            acc[nf][1] = acc[nf][1] * scale + da.y * tau_a;
            acc[nf][2] = acc[nf][2] * scale + db.x * tau_b2;
            acc[nf][3] = acc[nf][3] * scale + db.y * tau_b2;
            mn_a = fmaxf(mn_a, fmaxf(acc[nf][0], acc[nf][1]));
            mn_b = fmaxf(mn_b, fmaxf(acc[nf][2], acc[nf][3]));
        }
        mn_a = fmaxf(mn_a, __shfl_xor_sync(0xffffffffu, mn_a, 1));
        mn_a = fmaxf(mn_a, __shfl_xor_sync(0xffffffffu, mn_a, 2));
        mn_b = fmaxf(mn_b, __shfl_xor_sync(0xffffffffu, mn_b, 1));
        mn_b = fmaxf(mn_b, __shfl_xor_sync(0xffffffffu, mn_b, 2));

        const float mx_a = fmaxf(m_a, mn_a), mx_b = fmaxf(m_b, mn_b);
        const float al_a = __expf(m_a - mx_a), al_b = __expf(m_b - mx_b);
        m_a = mx_a; m_b = mx_b;

        float sum_a = 0.f, sum_b = 0.f;
        #pragma unroll
        for (int nf = 0; nf < 8; nf++) {
            acc[nf][0] = __expf(acc[nf][0] - mx_a);
            acc[nf][1] = __expf(acc[nf][1] - mx_a);
            acc[nf][2] = __expf(acc[nf][2] - mx_b);
            acc[nf][3] = __expf(acc[nf][3] - mx_b);
            sum_a += acc[nf][0] + acc[nf][1];
            sum_b += acc[nf][2] + acc[nf][3];
        }
        sum_a += __shfl_xor_sync(0xffffffffu, sum_a, 1);
        sum_a += __shfl_xor_sync(0xffffffffu, sum_a, 2);
        sum_b += __shfl_xor_sync(0xffffffffu, sum_b, 1);
        sum_b += __shfl_xor_sync(0xffffffffu, sum_b, 2);
        l_a = l_a * al_a + sum_a;
        l_b = l_b * al_b + sum_b;

        #pragma unroll
        for (int nf = 0; nf < 4; nf++) {
            O[nf][0] *= al_a; O[nf][1] *= al_a;
            O[nf][2] *= al_b; O[nf][3] *= al_b;
        }

        #pragma unroll
        for (int ks = 0; ks < 4; ks++) {
            uint32_t a[4];
            a[0] = packh2(acc[2 * ks][0],     acc[2 * ks][1]);
            a[1] = packh2(acc[2 * ks][2],     acc[2 * ks][3]);
            a[2] = packh2(acc[2 * ks + 1][0], acc[2 * ks + 1][1]);
            a[3] = packh2(acc[2 * ks + 1][2], acc[2 * ks + 1][3]);
            #pragma unroll
            for (int nfp = 0; nfp < 2; nfp++) {
                uint32_t vb4[4];
                ldsm4t(vb4, smaddr(&Vs[buf][(ks * 16 + r8a) * HSTR + nfp * 16 + c8a]));
                mma16(O[2 * nfp],     a, vb4[0], vb4[1]);
                mma16(O[2 * nfp + 1], a, vb4[2], vb4[3]);
            }
        }
        __syncthreads();
    }

    const float ia = 1.0f / l_a, ib = 1.0f / l_b;
    #pragma unroll
    for (int nf = 0; nf < 4; nf++) {
        *(__half2*)&ctxh[(size_t)(b * N_ + i0 + row_a) * D_ + h * HD_ + nf * 8 + 2 * t4]
            = __floats2half2_rn(O[nf][0] * ia, O[nf][1] * ia);
        *(__half2*)&ctxh[(size_t)(b * N_ + i0 + row_b) * D_ + h * HD_ + nf * 8 + 2 * t4]
            = __floats2half2_rn(O[nf][2] * ib, O[nf][3] * ib);
    }
}

// ---------------- launch ----------------------------------------------------
extern "C" void kernel_launch(void* const* d_in, const int* in_sizes, int n_in,
                              void* d_out, int out_size)
{
    const float* embed     = (const float*)d_in[0];
    // d_in[1] = refer_bbox (unused)
    const float* dist      = (const float*)d_in[2];
    const float* query_pos = (const float*)d_in[3];
    const float* in_proj_w = (const float*)d_in[4];
    const float* in_proj_b = (const float*)d_in[5];
    const float* out_w     = (const float*)d_in[6];
    const float* out_b     = (const float*)d_in[7];
    const float* tau_w     = (const float*)d_in[8];
    const float* tau_b     = (const float*)d_in[9];
    const float* w1        = (const float*)d_in[10];
    const float* b1        = (const float*)d_in[11];
    const float* w2        = (const float*)d_in[12];
    const float* b2        = (const float*)d_in[13];
    const float* g1        = (const float*)d_in[14];
    const float* beta1     = (const float*)d_in[15];
    const float* g2        = (const float*)d_in[16];
    const float* beta2     = (const float*)d_in[17];
    float* out = (float*)d_out;

    __half *p_qksh, *p_eh, *p_ipwh, *p_owh, *p_w1h, *p_w2h, *p_twh;
    __half *p_qkh, *p_vh, *p_ctxh, *p_xh, *p_hh;
    float *p_x;
    cudaGetSymbolAddress((void**)&p_qksh, g_qksum_h);
    cudaGetSymbolAddress((void**)&p_eh,   g_embed_h);
    cudaGetSymbolAddress((void**)&p_ipwh, g_ipw_h);
    cudaGetSymbolAddress((void**)&p_owh,  g_outw_h);
    cudaGetSymbolAddress((void**)&p_w1h,  g_w1_h);
    cudaGetSymbolAddress((void**)&p_w2h,  g_w2_h);
    cudaGetSymbolAddress((void**)&p_twh,  g_tauw_h);
    cudaGetSymbolAddress((void**)&p_qkh,  g_qk_h);
    cudaGetSymbolAddress((void**)&p_vh,   g_v_h);
    cudaGetSymbolAddress((void**)&p_ctxh, g_ctx_h);
    cudaGetSymbolAddress((void**)&p_xh,   g_x_h);
    cudaGetSymbolAddress((void**)&p_hh,   g_hh);
    cudaGetSymbolAddress((void**)&p_x,    g_x);

    const int gln_smem = 3 * (32 + 256) * HST * (int)sizeof(__half);  // 69120 B
    cudaFuncSetAttribute(gemm_ln_kernel, cudaFuncAttributeMaxDynamicSharedMemorySize, gln_smem);

    // 1. prep activations + convert all weights
    prepconv_kernel<<<(NP + S4 + 255) / 256, 256>>>(
        embed, query_pos, p_qksh, p_eh,
        in_proj_w, out_w, w1, w2, tau_w,
        p_ipwh, p_owh, p_w1h, p_w2h, p_twh);
    // 2. fused QKV projection (768 CTAs)
    qkv_kernel<<<dim3(12, ROWS / 64), 128>>>(p_qksh, p_eh, p_ipwh, in_proj_b, p_qkh, p_vh);
    // 3. flash attention (tau fused) -> ctx fp16
    flash_attn_kernel<<<dim3(N_ / BQ, B_ * H_), 256>>>(
        p_qkh, p_vh, p_eh, p_twh, tau_b, dist, p_ctxh);
    // 4. x = LN1(embed + ctx @ out_w^T + out_b)  [fused GEMM+res+LN]
    gemm_ln_kernel<<<ROWS / 32, 256, gln_smem>>>(
        p_ctxh, p_owh, out_b, embed, g1, beta1, p_x, p_xh, D_);
    // 5. h = relu(x @ w1^T + b1) -> fp16
    hgemm64_kernel<<<dim3(FFN_ / 64, ROWS / 64), 128>>>(
        p_xh, p_w1h, b1, nullptr, p_hh, FFN_, D_, 1, 1);
    // 6. out = LN2(x + h @ w2^T + b2)  [fused GEMM+res+LN]
    gemm_ln_kernel<<<ROWS / 32, 256, gln_smem>>>(
        p_hh, p_w2h, b2, p_x, g2, beta2, out, nullptr, FFN_);
}